// round 11
// baseline (speedup 1.0000x reference)
#include <cuda_runtime.h>
#include <cuda_fp16.h>
#include <stdint.h>

#define N_NODES_MAX 100000
#define N_EDGES_MAX 1600000
#define IN_FEAT 64
#define OUT_FEAT 64
#define NUM_BASES 4
#define NUM_RELS 8
#define KTOT 576                       // 8*64 relation-K + 64 self-loop K
#define N_BINS_MAX (N_NODES_MAX * NUM_RELS)

#define SCAN_T 1024
#define SCAN_NB ((N_BINS_MAX + SCAN_T - 1) / SCAN_T)   // 782

// Scratch (no proj2 anymore!)
__device__ __half g_feath[(size_t)N_NODES_MAX * IN_FEAT];   // fp16 feat, 12.8 MB (L2-resident)
__device__ __half g_wcat2[KTOT * OUT_FEAT];                 // [576, 64] fp16
__device__ int    g_count[N_BINS_MAX];
__device__ int    g_offset[N_BINS_MAX];
__device__ int    g_cursor[N_BINS_MAX];
__device__ int    g_bsum[SCAN_NB];
__device__ int2   g_edata[N_EDGES_MAX];     // bin-sorted {src, norm}

// ---------------------------------------------------------------------------
__global__ void zero_kernel(int n_bins)
{
    int i = blockIdx.x * blockDim.x + threadIdx.x;
    if (i < n_bins) g_count[i] = 0;
}

// feat fp32 -> fp16
__global__ void feath_kernel(const float* __restrict__ feat, int n_elems2)
{
    int i = blockIdx.x * blockDim.x + threadIdx.x;
    if (i < n_elems2) {
        float2 f = *(const float2*)&feat[i * 2];
        *(__half2*)&g_feath[i * 2] = __floats2half2_rn(f.x, f.y);
    }
}

// Wcat2[rk, o]: rk<512 -> sum_b w_comp[rk>>6,b]*weight[b, rk&63, o]; else loop_w
__global__ void wcat_kernel(const float* __restrict__ weight,
                            const float* __restrict__ w_comp,
                            const float* __restrict__ loop_w)
{
    int idx = blockIdx.x * blockDim.x + threadIdx.x;
    if (idx >= KTOT * OUT_FEAT) return;
    int rk = idx >> 6;
    int o = idx & 63;
    float v;
    if (rk < 512) {
        int r = rk >> 6, k = rk & 63;
        v = 0.0f;
        #pragma unroll
        for (int b = 0; b < NUM_BASES; ++b)
            v += w_comp[r * NUM_BASES + b] * weight[((size_t)b * 64 + k) * 64 + o];
    } else {
        v = loop_w[(size_t)(rk - 512) * 64 + o];
    }
    g_wcat2[idx] = __float2half_rn(v);
}

// ---------------------------------------------------------------------------
__global__ void hist_kernel(const int* __restrict__ dst,
                            const int* __restrict__ etypes, int n_edges)
{
    int i = blockIdx.x * blockDim.x + threadIdx.x;
    int e0 = i * 4;
    if (e0 + 4 <= n_edges) {
        int4 d = __ldg((const int4*)(dst + e0));
        int4 t = __ldg((const int4*)(etypes + e0));
        atomicAdd(&g_count[d.x * 8 + t.x], 1);
        atomicAdd(&g_count[d.y * 8 + t.y], 1);
        atomicAdd(&g_count[d.z * 8 + t.z], 1);
        atomicAdd(&g_count[d.w * 8 + t.w], 1);
    } else if (e0 < n_edges) {
        for (int e = e0; e < n_edges; ++e)
            atomicAdd(&g_count[__ldg(&dst[e]) * 8 + __ldg(&etypes[e])], 1);
    }
}

__global__ __launch_bounds__(SCAN_T) void scan_local_kernel(int n_bins)
{
    __shared__ int sh[SCAN_T];
    int i = blockIdx.x * SCAN_T + threadIdx.x;
    int c = (i < n_bins) ? g_count[i] : 0;
    sh[threadIdx.x] = c;
    __syncthreads();
    #pragma unroll
    for (int off = 1; off < SCAN_T; off <<= 1) {
        int v = (threadIdx.x >= off) ? sh[threadIdx.x - off] : 0;
        __syncthreads();
        sh[threadIdx.x] += v;
        __syncthreads();
    }
    if (i < n_bins) g_offset[i] = sh[threadIdx.x] - c;
    if (threadIdx.x == SCAN_T - 1) g_bsum[blockIdx.x] = sh[SCAN_T - 1];
}

__global__ __launch_bounds__(SCAN_T) void scan_bsum_kernel(int nb)
{
    __shared__ int sh[SCAN_T];
    int t = threadIdx.x;
    int c = (t < nb) ? g_bsum[t] : 0;
    sh[t] = c;
    __syncthreads();
    #pragma unroll
    for (int off = 1; off < SCAN_T; off <<= 1) {
        int v = (t >= off) ? sh[t - off] : 0;
        __syncthreads();
        sh[t] += v;
        __syncthreads();
    }
    if (t < nb) g_bsum[t] = sh[t] - c;
}

__global__ __launch_bounds__(SCAN_T) void scan_add_kernel(int n_bins)
{
    int i = blockIdx.x * SCAN_T + threadIdx.x;
    if (i < n_bins) {
        int o = g_offset[i] + g_bsum[blockIdx.x];
        g_offset[i] = o;
        g_cursor[i] = o;
    }
}

__global__ void scatter_kernel(const int* __restrict__ src,
                               const int* __restrict__ dst,
                               const int* __restrict__ etypes,
                               const float* __restrict__ norm,
                               int n_edges)
{
    int i = blockIdx.x * blockDim.x + threadIdx.x;
    int e0 = i * 4;
    if (e0 + 4 <= n_edges) {
        int4 s = __ldg((const int4*)(src + e0));
        int4 d = __ldg((const int4*)(dst + e0));
        int4 t = __ldg((const int4*)(etypes + e0));
        float4 nm = __ldg((const float4*)(norm + e0));
        int p0 = atomicAdd(&g_cursor[d.x * 8 + t.x], 1);
        int p1 = atomicAdd(&g_cursor[d.y * 8 + t.y], 1);
        int p2 = atomicAdd(&g_cursor[d.z * 8 + t.z], 1);
        int p3 = atomicAdd(&g_cursor[d.w * 8 + t.w], 1);
        g_edata[p0] = make_int2(s.x, __float_as_int(nm.x));
        g_edata[p1] = make_int2(s.y, __float_as_int(nm.y));
        g_edata[p2] = make_int2(s.z, __float_as_int(nm.z));
        g_edata[p3] = make_int2(s.w, __float_as_int(nm.w));
    } else if (e0 < n_edges) {
        for (int e = e0; e < n_edges; ++e) {
            int bin = __ldg(&dst[e]) * 8 + __ldg(&etypes[e]);
            int pos = atomicAdd(&g_cursor[bin], 1);
            g_edata[pos] = make_int2(__ldg(&src[e]), __float_as_int(__ldg(&norm[e])));
        }
    }
}

// ---------------------------------------------------------------------------
// mma.sync helpers
// ---------------------------------------------------------------------------
__device__ __forceinline__ uint32_t smem_u32(const void* p) {
    return (uint32_t)__cvta_generic_to_shared(p);
}

#define LDSM_X4(r0, r1, r2, r3, addr)                                          \
    asm volatile("ldmatrix.sync.aligned.m8n8.x4.shared.b16 {%0,%1,%2,%3}, [%4];" \
                 : "=r"(r0), "=r"(r1), "=r"(r2), "=r"(r3) : "r"(addr))

#define LDSM_X4_T(r0, r1, r2, r3, addr)                                        \
    asm volatile("ldmatrix.sync.aligned.m8n8.x4.trans.shared.b16 {%0,%1,%2,%3}, [%4];" \
                 : "=r"(r0), "=r"(r1), "=r"(r2), "=r"(r3) : "r"(addr))

#define MMA_16816(d, a, b)                                                     \
    asm volatile("mma.sync.aligned.m16n8k16.row.col.f32.f16.f16.f32 "          \
                 "{%0,%1,%2,%3}, {%4,%5,%6,%7}, {%8,%9}, {%0,%1,%2,%3};"       \
                 : "+f"(d[0]), "+f"(d[1]), "+f"(d[2]), "+f"(d[3])              \
                 : "r"(a[0]), "r"(a[1]), "r"(a[2]), "r"(a[3]),                 \
                   "r"(b[0]), "r"(b[1]))

// ---------------------------------------------------------------------------
// Fused kernel: per 64-node tile:
//   1. H_ext[64, 576] fp16 in smem: cols r*64.. = sum over run (norm*feat[src]),
//      cols 512..575 = fp16 feat of the dst rows (self-loop).
//   2. HMMA: out_tile = H_ext @ Wcat2 + bias   (Wcat2 fully smem-resident)
// 512 threads: agg = 64 nodes x 8 lanes; MMA = 16 warps, m16n16 each.
// ---------------------------------------------------------------------------
#define H_STRIDE 584   // 576 + 8 halves
#define WB_STRIDE 72   // 64 + 8 halves
#define SMEM_H_OFF 0
#define SMEM_W_OFF (64 * H_STRIDE)
#define FUSED_SMEM_HALVES (64 * H_STRIDE + KTOT * WB_STRIDE)
#define FUSED_SMEM_BYTES (FUSED_SMEM_HALVES * 2)   // 74752 + 82944 = 157696

__device__ __forceinline__ void acc8(float* acc, uint4 f, float nm)
{
    float2 p0 = __half22float2(*reinterpret_cast<__half2*>(&f.x));
    float2 p1 = __half22float2(*reinterpret_cast<__half2*>(&f.y));
    float2 p2 = __half22float2(*reinterpret_cast<__half2*>(&f.z));
    float2 p3 = __half22float2(*reinterpret_cast<__half2*>(&f.w));
    acc[0] += nm * p0.x; acc[1] += nm * p0.y;
    acc[2] += nm * p1.x; acc[3] += nm * p1.y;
    acc[4] += nm * p2.x; acc[5] += nm * p2.y;
    acc[6] += nm * p3.x; acc[7] += nm * p3.y;
}

__global__ __launch_bounds__(512) void fused_kernel(
    const float* __restrict__ h_bias,
    float* __restrict__ out,
    int n_nodes)
{
    extern __shared__ __align__(16) __half dyn[];
    __half* H  = dyn + SMEM_H_OFF;
    __half* WB = dyn + SMEM_W_OFF;

    const int tid = threadIdx.x;
    const int n0 = blockIdx.x * 64;

    // Load full Wcat2 [576, 64] -> WB (stride 72)
    #pragma unroll
    for (int i = tid; i < KTOT * 8; i += 512) {
        int row = i >> 3;
        int ch = i & 7;
        *(uint4*)&WB[row * WB_STRIDE + ch * 8] =
            *(const uint4*)&g_wcat2[row * OUT_FEAT + ch * 8];
    }
    // Zero H relation columns (0..511)
    #pragma unroll
    for (int i = tid; i < 64 * 64; i += 512) {
        int r = i >> 6;
        int ch = i & 63;
        *(uint4*)&H[r * H_STRIDE + ch * 8] = make_uint4(0, 0, 0, 0);
    }
    // Self-loop columns (512..575): fp16 feat of dst rows
    {
        int r = tid >> 3;
        int ch = tid & 7;
        int row = n0 + r;
        uint4 v = make_uint4(0, 0, 0, 0);
        if (row < n_nodes)
            v = *(const uint4*)&g_feath[(size_t)row * IN_FEAT + ch * 8];
        *(uint4*)&H[r * H_STRIDE + 512 + ch * 8] = v;
    }
    __syncthreads();

    // ---- Aggregation phase: 8 lanes per node ----
    {
        int hrow = tid >> 3;
        int lane = tid & 7;
        int node = n0 + hrow;
        if (node < n_nodes) {
            #pragma unroll
            for (int r = 0; r < NUM_RELS; ++r) {
                int bin = node * 8 + r;
                int start = __ldg(&g_offset[bin]);
                int cnt = __ldg(&g_count[bin]);
                if (cnt > 0) {
                    float acc[8] = {0, 0, 0, 0, 0, 0, 0, 0};
                    int j = 0;
                    for (; j + 2 <= cnt; j += 2) {
                        int2 e0 = __ldg(&g_edata[start + j]);
                        int2 e1 = __ldg(&g_edata[start + j + 1]);
                        uint4 f0 = __ldg((const uint4*)&g_feath[(size_t)e0.x * IN_FEAT + lane * 8]);
                        uint4 f1 = __ldg((const uint4*)&g_feath[(size_t)e1.x * IN_FEAT + lane * 8]);
                        acc8(acc, f0, __int_as_float(e0.y));
                        acc8(acc, f1, __int_as_float(e1.y));
                    }
                    if (j < cnt) {
                        int2 e = __ldg(&g_edata[start + j]);
                        uint4 f = __ldg((const uint4*)&g_feath[(size_t)e.x * IN_FEAT + lane * 8]);
                        acc8(acc, f, __int_as_float(e.y));
                    }
                    __half2 h0 = __floats2half2_rn(acc[0], acc[1]);
                    __half2 h1 = __floats2half2_rn(acc[2], acc[3]);
                    __half2 h2 = __floats2half2_rn(acc[4], acc[5]);
                    __half2 h3 = __floats2half2_rn(acc[6], acc[7]);
                    uint4 v;
                    v.x = *reinterpret_cast<unsigned int*>(&h0);
                    v.y = *reinterpret_cast<unsigned int*>(&h1);
                    v.z = *reinterpret_cast<unsigned int*>(&h2);
                    v.w = *reinterpret_cast<unsigned int*>(&h3);
                    *(uint4*)&H[hrow * H_STRIDE + r * 64 + lane * 8] = v;
                }
            }
        }
    }
    __syncthreads();

    // ---- MMA phase: 16 warps, each m16n16, K=576 ----
    {
        const int warp = tid >> 5;
        const int lane = tid & 31;
        const int wr = warp >> 2;      // 0..3: rows wr*16
        const int wc = warp & 3;       // 0..3: cols wc*16
        const int lrow = lane & 15;
        const int lcol = (lane >> 4) << 3;

        float acc[2][4];
        #pragma unroll
        for (int nj = 0; nj < 2; ++nj)
            #pragma unroll
            for (int q = 0; q < 4; ++q)
                acc[nj][q] = 0.0f;

        #pragma unroll 4
        for (int ks = 0; ks < KTOT / 16; ++ks) {
            uint32_t a[4];
            const __half* pa = &H[(wr * 16 + lrow) * H_STRIDE + ks * 16 + lcol];
            LDSM_X4(a[0], a[1], a[2], a[3], smem_u32(pa));
            uint32_t r0, r1, r2, r3;
            const __half* pb = &WB[(ks * 16 + lrow) * WB_STRIDE + wc * 16 + lcol];
            LDSM_X4_T(r0, r1, r2, r3, smem_u32(pb));
            uint32_t b0[2] = {r0, r1};
            uint32_t b1[2] = {r2, r3};
            MMA_16816(acc[0], a, b0);
            MMA_16816(acc[1], a, b1);
        }

        const int g = lane >> 2;
        const int tig = lane & 3;
        int ra = n0 + wr * 16 + g;
        int rb = ra + 8;
        #pragma unroll
        for (int nj = 0; nj < 2; ++nj) {
            int col = wc * 16 + nj * 8 + tig * 2;
            float b0 = h_bias[col];
            float b1 = h_bias[col + 1];
            if (ra < n_nodes)
                *(float2*)&out[(size_t)ra * OUT_FEAT + col] =
                    make_float2(acc[nj][0] + b0, acc[nj][1] + b1);
            if (rb < n_nodes)
                *(float2*)&out[(size_t)rb * OUT_FEAT + col] =
                    make_float2(acc[nj][2] + b0, acc[nj][3] + b1);
        }
    }
}

// ---------------------------------------------------------------------------
extern "C" void kernel_launch(void* const* d_in, const int* in_sizes, int n_in,
                              void* d_out, int out_size)
{
    const float* feat    = (const float*)d_in[0];
    const int*   src     = (const int*)d_in[1];
    const int*   dst     = (const int*)d_in[2];
    const int*   etypes  = (const int*)d_in[3];
    const float* norm    = (const float*)d_in[4];
    const float* weight  = (const float*)d_in[5];
    const float* w_comp  = (const float*)d_in[6];
    const float* h_bias  = (const float*)d_in[7];
    const float* loop_w  = (const float*)d_in[8];
    float*       out     = (float*)d_out;

    int n_nodes = in_sizes[0] / IN_FEAT;
    int n_edges = in_sizes[1];
    int n_bins = n_nodes * NUM_RELS;

    static bool attrSet = false;
    if (!attrSet) {
        cudaFuncSetAttribute(fused_kernel,
                             cudaFuncAttributeMaxDynamicSharedMemorySize,
                             FUSED_SMEM_BYTES);
        attrSet = true;
    }

    // Phase 0: fp16 feat, combined weights, zero bins
    feath_kernel<<<(n_nodes * 32 + 255) / 256, 256>>>(feat, n_nodes * 32);
    wcat_kernel<<<(KTOT * OUT_FEAT + 255) / 256, 256>>>(weight, w_comp, loop_w);
    zero_kernel<<<(n_bins + 255) / 256, 256>>>(n_bins);

    // Phase 1: counting sort by (dst, etype)
    int hthreads = (n_edges + 3) / 4;
    hist_kernel<<<(hthreads + 255) / 256, 256>>>(dst, etypes, n_edges);
    int nb = (n_bins + SCAN_T - 1) / SCAN_T;
    scan_local_kernel<<<nb, SCAN_T>>>(n_bins);
    scan_bsum_kernel<<<1, SCAN_T>>>(nb);
    scan_add_kernel<<<nb, SCAN_T>>>(n_bins);
    scatter_kernel<<<(hthreads + 255) / 256, 256>>>(src, dst, etypes, norm, n_edges);

    // Phase 2: fused aggregate + GEMM + bias + self-loop
    fused_kernel<<<(n_nodes + 63) / 64, 512, FUSED_SMEM_BYTES>>>(h_bias, out, n_nodes);
}

// round 12
// speedup vs baseline: 1.6549x; 1.6549x over previous
#include <cuda_runtime.h>
#include <cuda_fp16.h>
#include <stdint.h>

#define N_NODES_MAX 100000
#define N_EDGES_MAX 1600000
#define IN_FEAT 64
#define OUT_FEAT 64
#define NUM_BASES 4
#define NUM_RELS 8
#define P2_COLS (NUM_RELS * OUT_FEAT)      // 512
#define WCAT_COLS (P2_COLS + OUT_FEAT)     // 576

#define SCAN_T 1024
#define SCAN_NB ((N_NODES_MAX + SCAN_T - 1) / SCAN_T)

// Scratch
__device__ __half g_proj2[(size_t)N_NODES_MAX * P2_COLS];   // ~102.4 MB
__device__ __half g_wcat[IN_FEAT * WCAT_COLS];
__device__ int    g_count[N_NODES_MAX];
__device__ int    g_offset[N_NODES_MAX];
__device__ int    g_cursor[N_NODES_MAX];
__device__ int    g_bsum[SCAN_NB];
__device__ int2   g_edata[N_EDGES_MAX];     // dst-sorted {src|etype<<20, norm}

// ---------------------------------------------------------------------------
__global__ void zero_kernel(int n_nodes)
{
    int i = blockIdx.x * blockDim.x + threadIdx.x;
    if (i < n_nodes) g_count[i] = 0;
}

__global__ void wcat_kernel(const float* __restrict__ weight,
                            const float* __restrict__ w_comp,
                            const float* __restrict__ loop_w)
{
    int idx = blockIdx.x * blockDim.x + threadIdx.x;
    if (idx >= IN_FEAT * WCAT_COLS) return;
    int k = idx / WCAT_COLS;
    int n = idx % WCAT_COLS;
    float v;
    if (n < P2_COLS) {
        int r = n >> 6, o = n & 63;
        v = 0.0f;
        #pragma unroll
        for (int b = 0; b < NUM_BASES; ++b)
            v += w_comp[r * NUM_BASES + b] * weight[((size_t)b * 64 + k) * 64 + o];
    } else {
        v = loop_w[(size_t)k * 64 + (n - P2_COLS)];
    }
    g_wcat[idx] = __float2half_rn(v);
}

// ---------------------------------------------------------------------------
__device__ __forceinline__ uint32_t smem_u32(const void* p) {
    return (uint32_t)__cvta_generic_to_shared(p);
}

#define LDSM_X4(r0, r1, r2, r3, addr)                                          \
    asm volatile("ldmatrix.sync.aligned.m8n8.x4.shared.b16 {%0,%1,%2,%3}, [%4];" \
                 : "=r"(r0), "=r"(r1), "=r"(r2), "=r"(r3) : "r"(addr))

#define LDSM_X4_T(r0, r1, r2, r3, addr)                                        \
    asm volatile("ldmatrix.sync.aligned.m8n8.x4.trans.shared.b16 {%0,%1,%2,%3}, [%4];" \
                 : "=r"(r0), "=r"(r1), "=r"(r2), "=r"(r3) : "r"(addr))

#define MMA_16816(d, a, b)                                                     \
    asm volatile("mma.sync.aligned.m16n8k16.row.col.f32.f16.f16.f32 "          \
                 "{%0,%1,%2,%3}, {%4,%5,%6,%7}, {%8,%9}, {%0,%1,%2,%3};"       \
                 : "+f"(d[0]), "+f"(d[1]), "+f"(d[2]), "+f"(d[3])              \
                 : "r"(a[0]), "r"(a[1]), "r"(a[2]), "r"(a[3]),                 \
                   "r"(b[0]), "r"(b[1]))

// ---------------------------------------------------------------------------
// Kernel A: proj2 (fp16) + out-init (fp32) via HMMA.
//   R12: per-pass B loading (46 KB smem -> 3-4 blocks/SM), staged copy-out.
// ---------------------------------------------------------------------------
#define SA_STRIDE 72
#define SBP_STRIDE 72
#define SS_STRIDE 72

#define SMEM_A_OFF 0
#define SMEM_B_OFF (128 * SA_STRIDE)
#define SMEM_S_OFF (128 * SA_STRIDE + 64 * SBP_STRIDE)
#define SMEM_HALVES (128 * SA_STRIDE + 64 * SBP_STRIDE + 128 * SS_STRIDE)
#define SMEM_BYTES (SMEM_HALVES * 2)   // 46080 B

__global__ __launch_bounds__(256, 3) void rgcn_mma_kernel(
    const float* __restrict__ feat,
    const float* __restrict__ h_bias,
    float* __restrict__ out,
    int n_nodes)
{
    extern __shared__ __align__(16) __half dyn[];
    __half* sA = dyn + SMEM_A_OFF;
    __half* sB = dyn + SMEM_B_OFF;
    __half* sS = dyn + SMEM_S_OFF;

    const int tid = threadIdx.x;
    const int row0 = blockIdx.x * 128;
    const bool fullTile = (row0 + 128 <= n_nodes);

    // Load A tile (128 x 64), fp32 -> fp16
    #pragma unroll
    for (int i = tid; i < 128 * 32; i += 256) {
        int r = i >> 5;
        int cpair = i & 31;
        int row = row0 + r;
        float2 f = (row < n_nodes)
                     ? *(const float2*)&feat[(size_t)row * IN_FEAT + cpair * 2]
                     : make_float2(0.0f, 0.0f);
        *(__half2*)&sA[r * SA_STRIDE + cpair * 2] = __floats2half2_rn(f.x, f.y);
    }

    const int warp = tid >> 5;
    const int lane = tid & 31;
    const int wr = warp >> 1;
    const int wc = warp & 1;
    const int lrow = lane & 15;
    const int lcol = (lane >> 4) << 3;
    const int g   = lane >> 2;
    const int tig = lane & 3;

    for (int cp = 0; cp < 9; ++cp) {
        __syncthreads();   // A ready (iter 0) / prev LDSM-B + stage copy done
        // Load B slice for this pass: g_wcat[k][cp*64 + c], 64 x 64
        #pragma unroll
        for (int i = tid; i < 512; i += 256) {
            int r = i >> 3;
            int ch = i & 7;
            *(uint4*)&sB[r * SBP_STRIDE + ch * 8] =
                *(const uint4*)&g_wcat[(size_t)r * WCAT_COLS + cp * 64 + ch * 8];
        }
        __syncthreads();

        float acc[2][4][4];
        #pragma unroll
        for (int mi = 0; mi < 2; ++mi)
            #pragma unroll
            for (int nj = 0; nj < 4; ++nj)
                #pragma unroll
                for (int q = 0; q < 4; ++q)
                    acc[mi][nj][q] = 0.0f;

        #pragma unroll
        for (int ks = 0; ks < 4; ++ks) {
            uint32_t a[2][4];
            #pragma unroll
            for (int mi = 0; mi < 2; ++mi) {
                const __half* p = &sA[(wr * 32 + mi * 16 + lrow) * SA_STRIDE
                                      + ks * 16 + lcol];
                LDSM_X4(a[mi][0], a[mi][1], a[mi][2], a[mi][3], smem_u32(p));
            }
            uint32_t b[4][2];
            #pragma unroll
            for (int np = 0; np < 2; ++np) {
                const __half* p = &sB[(ks * 16 + lrow) * SBP_STRIDE
                                      + wc * 32 + np * 16 + lcol];
                uint32_t r0, r1, r2, r3;
                LDSM_X4_T(r0, r1, r2, r3, smem_u32(p));
                b[np * 2 + 0][0] = r0; b[np * 2 + 0][1] = r1;
                b[np * 2 + 1][0] = r2; b[np * 2 + 1][1] = r3;
            }
            #pragma unroll
            for (int mi = 0; mi < 2; ++mi)
                #pragma unroll
                for (int nj = 0; nj < 4; ++nj)
                    MMA_16816(acc[mi][nj], a[mi], b[nj]);
        }

        if (cp < 8) {
            __syncthreads();   // prev copy-out done before overwriting stage
            #pragma unroll
            for (int mi = 0; mi < 2; ++mi) {
                int rta = wr * 32 + mi * 16 + g;
                int rtb = rta + 8;
                #pragma unroll
                for (int nj = 0; nj < 4; ++nj) {
                    int col = wc * 32 + nj * 8 + tig * 2;
                    *(__half2*)&sS[rta * SS_STRIDE + col] =
                        __floats2half2_rn(acc[mi][nj][0], acc[mi][nj][1]);
                    *(__half2*)&sS[rtb * SS_STRIDE + col] =
                        __floats2half2_rn(acc[mi][nj][2], acc[mi][nj][3]);
                }
            }
            __syncthreads();
            if (fullTile) {
                #pragma unroll
                for (int i = tid; i < 1024; i += 256) {
                    int r = i >> 3;
                    int ch = i & 7;
                    uint4 v = *(const uint4*)&sS[r * SS_STRIDE + ch * 8];
                    *(uint4*)&g_proj2[(size_t)(row0 + r) * P2_COLS
                                      + cp * OUT_FEAT + ch * 8] = v;
                }
            } else {
                #pragma unroll
                for (int i = tid; i < 1024; i += 256) {
                    int r = i >> 3;
                    int ch = i & 7;
                    int row = row0 + r;
                    if (row < n_nodes) {
                        uint4 v = *(const uint4*)&sS[r * SS_STRIDE + ch * 8];
                        *(uint4*)&g_proj2[(size_t)row * P2_COLS
                                          + cp * OUT_FEAT + ch * 8] = v;
                    }
                }
            }
        } else {
            #pragma unroll
            for (int mi = 0; mi < 2; ++mi) {
                int ra = row0 + wr * 32 + mi * 16 + g;
                int rb = ra + 8;
                #pragma unroll
                for (int nj = 0; nj < 4; ++nj) {
                    int col = wc * 32 + nj * 8 + tig * 2;
                    float b0 = h_bias[col];
                    float b1 = h_bias[col + 1];
                    if (ra < n_nodes)
                        *(float2*)&out[(size_t)ra * OUT_FEAT + col] =
                            make_float2(acc[mi][nj][0] + b0, acc[mi][nj][1] + b1);
                    if (rb < n_nodes)
                        *(float2*)&out[(size_t)rb * OUT_FEAT + col] =
                            make_float2(acc[mi][nj][2] + b0, acc[mi][nj][3] + b1);
                }
            }
        }
    }
}

// ---------------------------------------------------------------------------
__global__ void hist_kernel(const int* __restrict__ dst, int n_edges)
{
    int i = blockIdx.x * blockDim.x + threadIdx.x;
    int e0 = i * 4;
    if (e0 + 4 <= n_edges) {
        int4 d = __ldg((const int4*)(dst + e0));
        atomicAdd(&g_count[d.x], 1);
        atomicAdd(&g_count[d.y], 1);
        atomicAdd(&g_count[d.z], 1);
        atomicAdd(&g_count[d.w], 1);
    } else if (e0 < n_edges) {
        for (int e = e0; e < n_edges; ++e)
            atomicAdd(&g_count[__ldg(&dst[e])], 1);
    }
}

__global__ __launch_bounds__(SCAN_T) void scan_local_kernel(int n_nodes)
{
    __shared__ int sh[SCAN_T];
    int i = blockIdx.x * SCAN_T + threadIdx.x;
    int c = (i < n_nodes) ? g_count[i] : 0;
    sh[threadIdx.x] = c;
    __syncthreads();
    #pragma unroll
    for (int off = 1; off < SCAN_T; off <<= 1) {
        int v = (threadIdx.x >= off) ? sh[threadIdx.x - off] : 0;
        __syncthreads();
        sh[threadIdx.x] += v;
        __syncthreads();
    }
    if (i < n_nodes) g_offset[i] = sh[threadIdx.x] - c;
    if (threadIdx.x == SCAN_T - 1) g_bsum[blockIdx.x] = sh[SCAN_T - 1];
}

__global__ __launch_bounds__(128) void scan_bsum_kernel(int nb)
{
    __shared__ int sh[128];
    int t = threadIdx.x;
    int c = (t < nb) ? g_bsum[t] : 0;
    sh[t] = c;
    __syncthreads();
    #pragma unroll
    for (int off = 1; off < 128; off <<= 1) {
        int v = (t >= off) ? sh[t - off] : 0;
        __syncthreads();
        sh[t] += v;
        __syncthreads();
    }
    if (t < nb) g_bsum[t] = sh[t] - c;
}

__global__ __launch_bounds__(SCAN_T) void scan_add_kernel(int n_nodes)
{
    int i = blockIdx.x * SCAN_T + threadIdx.x;
    if (i < n_nodes) {
        int o = g_offset[i] + g_bsum[blockIdx.x];
        g_offset[i] = o;
        g_cursor[i] = o;
    }
}

__global__ void scatter_kernel(const int* __restrict__ src,
                               const int* __restrict__ dst,
                               const int* __restrict__ etypes,
                               const float* __restrict__ norm,
                               int n_edges)
{
    int i = blockIdx.x * blockDim.x + threadIdx.x;
    int e0 = i * 4;
    if (e0 + 4 <= n_edges) {
        int4 s = __ldg((const int4*)(src + e0));
        int4 d = __ldg((const int4*)(dst + e0));
        int4 t = __ldg((const int4*)(etypes + e0));
        float4 nm = __ldg((const float4*)(norm + e0));
        int p0 = atomicAdd(&g_cursor[d.x], 1);
        int p1 = atomicAdd(&g_cursor[d.y], 1);
        int p2 = atomicAdd(&g_cursor[d.z], 1);
        int p3 = atomicAdd(&g_cursor[d.w], 1);
        g_edata[p0] = make_int2(s.x | (t.x << 20), __float_as_int(nm.x));
        g_edata[p1] = make_int2(s.y | (t.y << 20), __float_as_int(nm.y));
        g_edata[p2] = make_int2(s.z | (t.z << 20), __float_as_int(nm.z));
        g_edata[p3] = make_int2(s.w | (t.w << 20), __float_as_int(nm.w));
    } else if (e0 < n_edges) {
        for (int e = e0; e < n_edges; ++e) {
            int d = __ldg(&dst[e]);
            int pos = atomicAdd(&g_cursor[d], 1);
            g_edata[pos] = make_int2(__ldg(&src[e]) | (__ldg(&etypes[e]) << 20),
                                     __float_as_int(__ldg(&norm[e])));
        }
    }
}

// ---------------------------------------------------------------------------
// Kernel 4: per-node aggregation, 8 lanes/node, uint4 gathers (R8 exact)
// ---------------------------------------------------------------------------
__device__ __forceinline__ void acc_msg(float4& a, float4& b, uint4 raw, float nm)
{
    float2 f0 = __half22float2(*reinterpret_cast<__half2*>(&raw.x));
    float2 f1 = __half22float2(*reinterpret_cast<__half2*>(&raw.y));
    float2 f2 = __half22float2(*reinterpret_cast<__half2*>(&raw.z));
    float2 f3 = __half22float2(*reinterpret_cast<__half2*>(&raw.w));
    a.x += f0.x * nm; a.y += f0.y * nm; a.z += f1.x * nm; a.w += f1.y * nm;
    b.x += f2.x * nm; b.y += f2.y * nm; b.z += f3.x * nm; b.w += f3.y * nm;
}

__global__ __launch_bounds__(256) void agg_kernel(
    float* __restrict__ out, int n_nodes)
{
    int gidx = blockIdx.x * 256 + threadIdx.x;
    int node = gidx >> 3;
    int lane = gidx & 7;
    if (node >= n_nodes) return;

    int start = __ldg(&g_offset[node]);
    int deg   = __ldg(&g_count[node]);

    float4 accA = *(float4*)&out[(size_t)node * OUT_FEAT + lane * 8];
    float4 accB = *(float4*)&out[(size_t)node * OUT_FEAT + lane * 8 + 4];

    int j = 0;
    for (; j + 4 <= deg; j += 4) {
        int2 e0 = __ldg(&g_edata[start + j + 0]);
        int2 e1 = __ldg(&g_edata[start + j + 1]);
        int2 e2 = __ldg(&g_edata[start + j + 2]);
        int2 e3 = __ldg(&g_edata[start + j + 3]);
        uint4 r0 = __ldg((const uint4*)(g_proj2 +
            ((size_t)(e0.x & 0xFFFFF) * P2_COLS + (e0.x >> 20) * OUT_FEAT + lane * 8)));
        uint4 r1 = __ldg((const uint4*)(g_proj2 +
            ((size_t)(e1.x & 0xFFFFF) * P2_COLS + (e1.x >> 20) * OUT_FEAT + lane * 8)));
        uint4 r2 = __ldg((const uint4*)(g_proj2 +
            ((size_t)(e2.x & 0xFFFFF) * P2_COLS + (e2.x >> 20) * OUT_FEAT + lane * 8)));
        uint4 r3 = __ldg((const uint4*)(g_proj2 +
            ((size_t)(e3.x & 0xFFFFF) * P2_COLS + (e3.x >> 20) * OUT_FEAT + lane * 8)));
        acc_msg(accA, accB, r0, __int_as_float(e0.y));
        acc_msg(accA, accB, r1, __int_as_float(e1.y));
        acc_msg(accA, accB, r2, __int_as_float(e2.y));
        acc_msg(accA, accB, r3, __int_as_float(e3.y));
    }
    for (; j < deg; ++j) {
        int2 ed = __ldg(&g_edata[start + j]);
        uint4 raw = __ldg((const uint4*)(g_proj2 +
            ((size_t)(ed.x & 0xFFFFF) * P2_COLS + (ed.x >> 20) * OUT_FEAT + lane * 8)));
        acc_msg(accA, accB, raw, __int_as_float(ed.y));
    }

    *(float4*)&out[(size_t)node * OUT_FEAT + lane * 8]     = accA;
    *(float4*)&out[(size_t)node * OUT_FEAT + lane * 8 + 4] = accB;
}

// ---------------------------------------------------------------------------
extern "C" void kernel_launch(void* const* d_in, const int* in_sizes, int n_in,
                              void* d_out, int out_size)
{
    const float* feat    = (const float*)d_in[0];
    const int*   src     = (const int*)d_in[1];
    const int*   dst     = (const int*)d_in[2];
    const int*   etypes  = (const int*)d_in[3];
    const float* norm    = (const float*)d_in[4];
    const float* weight  = (const float*)d_in[5];
    const float* w_comp  = (const float*)d_in[6];
    const float* h_bias  = (const float*)d_in[7];
    const float* loop_w  = (const float*)d_in[8];
    float*       out     = (float*)d_out;

    int n_nodes = in_sizes[0] / IN_FEAT;
    int n_edges = in_sizes[1];

    static bool attrSet = false;
    if (!attrSet) {
        cudaFuncSetAttribute(rgcn_mma_kernel,
                             cudaFuncAttributeMaxDynamicSharedMemorySize, SMEM_BYTES);
        attrSet = true;
    }

    // Phase 0
    zero_kernel<<<(n_nodes + 255) / 256, 256>>>(n_nodes);
    wcat_kernel<<<(IN_FEAT * WCAT_COLS + 255) / 256, 256>>>(weight, w_comp, loop_w);

    // Phase 1: HMMA GEMM
    rgcn_mma_kernel<<<(n_nodes + 127) / 128, 256, SMEM_BYTES>>>(feat, h_bias, out, n_nodes);

    // Phase 2: counting sort by dst
    int hthreads = (n_edges + 3) / 4;
    hist_kernel<<<(hthreads + 255) / 256, 256>>>(dst, n_edges);
    int nb = (n_nodes + SCAN_T - 1) / SCAN_T;
    scan_local_kernel<<<nb, SCAN_T>>>(n_nodes);
    scan_bsum_kernel<<<1, 128>>>(nb);
    scan_add_kernel<<<nb, SCAN_T>>>(n_nodes);
    scatter_kernel<<<(hthreads + 255) / 256, 256>>>(src, dst, etypes, norm, n_edges);

    // Phase 3: atomic-free aggregation
    long long total_threads = (long long)n_nodes * 8;
    agg_kernel<<<(int)((total_threads + 255) / 256), 256>>>(out, n_nodes);
}

// round 13
// speedup vs baseline: 1.7031x; 1.0291x over previous
#include <cuda_runtime.h>
#include <cuda_fp16.h>
#include <stdint.h>

#define N_NODES_MAX 100000
#define N_EDGES_MAX 1600000
#define IN_FEAT 64
#define OUT_FEAT 64
#define NUM_BASES 4
#define NUM_RELS 8
#define P2_COLS (NUM_RELS * OUT_FEAT)      // 512
#define WCAT_COLS (P2_COLS + OUT_FEAT)     // 576

#define SCAN_T 1024
#define SCAN_NB ((N_NODES_MAX + SCAN_T - 1) / SCAN_T)

// Scratch
__device__ __half g_proj2[(size_t)N_NODES_MAX * P2_COLS];   // ~102.4 MB
__device__ __half g_wcat[IN_FEAT * WCAT_COLS];
__device__ int    g_count[N_NODES_MAX];
__device__ int    g_offset[N_NODES_MAX];
__device__ int    g_cursor[N_NODES_MAX];
__device__ int    g_bsum[SCAN_NB];
__device__ int2   g_edata[N_EDGES_MAX];     // dst-sorted {src|etype<<20, norm}

// ---------------------------------------------------------------------------
__global__ void zero_kernel(int n_nodes)
{
    int i = blockIdx.x * blockDim.x + threadIdx.x;
    if (i < n_nodes) g_count[i] = 0;
}

__global__ void wcat_kernel(const float* __restrict__ weight,
                            const float* __restrict__ w_comp,
                            const float* __restrict__ loop_w)
{
    int idx = blockIdx.x * blockDim.x + threadIdx.x;
    if (idx >= IN_FEAT * WCAT_COLS) return;
    int k = idx / WCAT_COLS;
    int n = idx % WCAT_COLS;
    float v;
    if (n < P2_COLS) {
        int r = n >> 6, o = n & 63;
        v = 0.0f;
        #pragma unroll
        for (int b = 0; b < NUM_BASES; ++b)
            v += w_comp[r * NUM_BASES + b] * weight[((size_t)b * 64 + k) * 64 + o];
    } else {
        v = loop_w[(size_t)k * 64 + (n - P2_COLS)];
    }
    g_wcat[idx] = __float2half_rn(v);
}

// ---------------------------------------------------------------------------
__device__ __forceinline__ uint32_t smem_u32(const void* p) {
    return (uint32_t)__cvta_generic_to_shared(p);
}

#define LDSM_X4(r0, r1, r2, r3, addr)                                          \
    asm volatile("ldmatrix.sync.aligned.m8n8.x4.shared.b16 {%0,%1,%2,%3}, [%4];" \
                 : "=r"(r0), "=r"(r1), "=r"(r2), "=r"(r3) : "r"(addr))

#define LDSM_X4_T(r0, r1, r2, r3, addr)                                        \
    asm volatile("ldmatrix.sync.aligned.m8n8.x4.trans.shared.b16 {%0,%1,%2,%3}, [%4];" \
                 : "=r"(r0), "=r"(r1), "=r"(r2), "=r"(r3) : "r"(addr))

#define MMA_16816(d, a, b)                                                     \
    asm volatile("mma.sync.aligned.m16n8k16.row.col.f32.f16.f16.f32 "          \
                 "{%0,%1,%2,%3}, {%4,%5,%6,%7}, {%8,%9}, {%0,%1,%2,%3};"       \
                 : "+f"(d[0]), "+f"(d[1]), "+f"(d[2]), "+f"(d[3])              \
                 : "r"(a[0]), "r"(a[1]), "r"(a[2]), "r"(a[3]),                 \
                   "r"(b[0]), "r"(b[1]))

// ---------------------------------------------------------------------------
// Kernel A: proj2 (fp16) + out-init (fp32) via HMMA, R12 structure
//   + R13: embedded grid-stride dst-histogram prologue (fills MMA idle issue).
// ---------------------------------------------------------------------------
#define SA_STRIDE 72
#define SBP_STRIDE 72
#define SS_STRIDE 72

#define SMEM_A_OFF 0
#define SMEM_B_OFF (128 * SA_STRIDE)
#define SMEM_S_OFF (128 * SA_STRIDE + 64 * SBP_STRIDE)
#define SMEM_HALVES (128 * SA_STRIDE + 64 * SBP_STRIDE + 128 * SS_STRIDE)
#define SMEM_BYTES (SMEM_HALVES * 2)   // 46080 B

__global__ __launch_bounds__(256, 3) void rgcn_mma_kernel(
    const float* __restrict__ feat,
    const float* __restrict__ h_bias,
    const int*   __restrict__ dst,
    float* __restrict__ out,
    int n_nodes, int n_edges)
{
    extern __shared__ __align__(16) __half dyn[];
    __half* sA = dyn + SMEM_A_OFF;
    __half* sB = dyn + SMEM_B_OFF;
    __half* sS = dyn + SMEM_S_OFF;

    const int tid = threadIdx.x;
    const int row0 = blockIdx.x * 128;
    const bool fullTile = (row0 + 128 <= n_nodes);

    // --- Embedded histogram: fire-and-forget REDs, independent of GEMM ---
    {
        int quads = (n_edges + 3) >> 2;
        for (int q = blockIdx.x * 256 + tid; q < quads; q += gridDim.x * 256) {
            int e0 = q * 4;
            if (e0 + 4 <= n_edges) {
                int4 d = __ldg((const int4*)(dst + e0));
                atomicAdd(&g_count[d.x], 1);
                atomicAdd(&g_count[d.y], 1);
                atomicAdd(&g_count[d.z], 1);
                atomicAdd(&g_count[d.w], 1);
            } else {
                for (int e = e0; e < n_edges; ++e)
                    atomicAdd(&g_count[__ldg(&dst[e])], 1);
            }
        }
    }

    // Load A tile (128 x 64), fp32 -> fp16
    #pragma unroll
    for (int i = tid; i < 128 * 32; i += 256) {
        int r = i >> 5;
        int cpair = i & 31;
        int row = row0 + r;
        float2 f = (row < n_nodes)
                     ? *(const float2*)&feat[(size_t)row * IN_FEAT + cpair * 2]
                     : make_float2(0.0f, 0.0f);
        *(__half2*)&sA[r * SA_STRIDE + cpair * 2] = __floats2half2_rn(f.x, f.y);
    }

    const int warp = tid >> 5;
    const int lane = tid & 31;
    const int wr = warp >> 1;
    const int wc = warp & 1;
    const int lrow = lane & 15;
    const int lcol = (lane >> 4) << 3;
    const int g   = lane >> 2;
    const int tig = lane & 3;

    for (int cp = 0; cp < 9; ++cp) {
        __syncthreads();   // A ready (iter 0) / prev LDSM-B + stage copy done
        // Load B slice for this pass: g_wcat[k][cp*64 + c], 64 x 64
        #pragma unroll
        for (int i = tid; i < 512; i += 256) {
            int r = i >> 3;
            int ch = i & 7;
            *(uint4*)&sB[r * SBP_STRIDE + ch * 8] =
                *(const uint4*)&g_wcat[(size_t)r * WCAT_COLS + cp * 64 + ch * 8];
        }
        __syncthreads();

        float acc[2][4][4];
        #pragma unroll
        for (int mi = 0; mi < 2; ++mi)
            #pragma unroll
            for (int nj = 0; nj < 4; ++nj)
                #pragma unroll
                for (int q = 0; q < 4; ++q)
                    acc[mi][nj][q] = 0.0f;

        #pragma unroll
        for (int ks = 0; ks < 4; ++ks) {
            uint32_t a[2][4];
            #pragma unroll
            for (int mi = 0; mi < 2; ++mi) {
                const __half* p = &sA[(wr * 32 + mi * 16 + lrow) * SA_STRIDE
                                      + ks * 16 + lcol];
                LDSM_X4(a[mi][0], a[mi][1], a[mi][2], a[mi][3], smem_u32(p));
            }
            uint32_t b[4][2];
            #pragma unroll
            for (int np = 0; np < 2; ++np) {
                const __half* p = &sB[(ks * 16 + lrow) * SBP_STRIDE
                                      + wc * 32 + np * 16 + lcol];
                uint32_t r0, r1, r2, r3;
                LDSM_X4_T(r0, r1, r2, r3, smem_u32(p));
                b[np * 2 + 0][0] = r0; b[np * 2 + 0][1] = r1;
                b[np * 2 + 1][0] = r2; b[np * 2 + 1][1] = r3;
            }
            #pragma unroll
            for (int mi = 0; mi < 2; ++mi)
                #pragma unroll
                for (int nj = 0; nj < 4; ++nj)
                    MMA_16816(acc[mi][nj], a[mi], b[nj]);
        }

        if (cp < 8) {
            __syncthreads();   // prev copy-out done before overwriting stage
            #pragma unroll
            for (int mi = 0; mi < 2; ++mi) {
                int rta = wr * 32 + mi * 16 + g;
                int rtb = rta + 8;
                #pragma unroll
                for (int nj = 0; nj < 4; ++nj) {
                    int col = wc * 32 + nj * 8 + tig * 2;
                    *(__half2*)&sS[rta * SS_STRIDE + col] =
                        __floats2half2_rn(acc[mi][nj][0], acc[mi][nj][1]);
                    *(__half2*)&sS[rtb * SS_STRIDE + col] =
                        __floats2half2_rn(acc[mi][nj][2], acc[mi][nj][3]);
                }
            }
            __syncthreads();
            if (fullTile) {
                #pragma unroll
                for (int i = tid; i < 1024; i += 256) {
                    int r = i >> 3;
                    int ch = i & 7;
                    uint4 v = *(const uint4*)&sS[r * SS_STRIDE + ch * 8];
                    *(uint4*)&g_proj2[(size_t)(row0 + r) * P2_COLS
                                      + cp * OUT_FEAT + ch * 8] = v;
                }
            } else {
                #pragma unroll
                for (int i = tid; i < 1024; i += 256) {
                    int r = i >> 3;
                    int ch = i & 7;
                    int row = row0 + r;
                    if (row < n_nodes) {
                        uint4 v = *(const uint4*)&sS[r * SS_STRIDE + ch * 8];
                        *(uint4*)&g_proj2[(size_t)row * P2_COLS
                                          + cp * OUT_FEAT + ch * 8] = v;
                    }
                }
            }
        } else {
            #pragma unroll
            for (int mi = 0; mi < 2; ++mi) {
                int ra = row0 + wr * 32 + mi * 16 + g;
                int rb = ra + 8;
                #pragma unroll
                for (int nj = 0; nj < 4; ++nj) {
                    int col = wc * 32 + nj * 8 + tig * 2;
                    float b0 = h_bias[col];
                    float b1 = h_bias[col + 1];
                    if (ra < n_nodes)
                        *(float2*)&out[(size_t)ra * OUT_FEAT + col] =
                            make_float2(acc[mi][nj][0] + b0, acc[mi][nj][1] + b1);
                    if (rb < n_nodes)
                        *(float2*)&out[(size_t)rb * OUT_FEAT + col] =
                            make_float2(acc[mi][nj][2] + b0, acc[mi][nj][3] + b1);
                }
            }
        }
    }
}

// ---------------------------------------------------------------------------
__global__ __launch_bounds__(SCAN_T) void scan_local_kernel(int n_nodes)
{
    __shared__ int sh[SCAN_T];
    int i = blockIdx.x * SCAN_T + threadIdx.x;
    int c = (i < n_nodes) ? g_count[i] : 0;
    sh[threadIdx.x] = c;
    __syncthreads();
    #pragma unroll
    for (int off = 1; off < SCAN_T; off <<= 1) {
        int v = (threadIdx.x >= off) ? sh[threadIdx.x - off] : 0;
        __syncthreads();
        sh[threadIdx.x] += v;
        __syncthreads();
    }
    if (i < n_nodes) g_offset[i] = sh[threadIdx.x] - c;
    if (threadIdx.x == SCAN_T - 1) g_bsum[blockIdx.x] = sh[SCAN_T - 1];
}

__global__ __launch_bounds__(128) void scan_bsum_kernel(int nb)
{
    __shared__ int sh[128];
    int t = threadIdx.x;
    int c = (t < nb) ? g_bsum[t] : 0;
    sh[t] = c;
    __syncthreads();
    #pragma unroll
    for (int off = 1; off < 128; off <<= 1) {
        int v = (t >= off) ? sh[t - off] : 0;
        __syncthreads();
        sh[t] += v;
        __syncthreads();
    }
    if (t < nb) g_bsum[t] = sh[t] - c;
}

__global__ __launch_bounds__(SCAN_T) void scan_add_kernel(int n_nodes)
{
    int i = blockIdx.x * SCAN_T + threadIdx.x;
    if (i < n_nodes) {
        int o = g_offset[i] + g_bsum[blockIdx.x];
        g_offset[i] = o;
        g_cursor[i] = o;
    }
}

__global__ void scatter_kernel(const int* __restrict__ src,
                               const int* __restrict__ dst,
                               const int* __restrict__ etypes,
                               const float* __restrict__ norm,
                               int n_edges)
{
    int i = blockIdx.x * blockDim.x + threadIdx.x;
    int e0 = i * 4;
    if (e0 + 4 <= n_edges) {
        int4 s = __ldg((const int4*)(src + e0));
        int4 d = __ldg((const int4*)(dst + e0));
        int4 t = __ldg((const int4*)(etypes + e0));
        float4 nm = __ldg((const float4*)(norm + e0));
        int p0 = atomicAdd(&g_cursor[d.x], 1);
        int p1 = atomicAdd(&g_cursor[d.y], 1);
        int p2 = atomicAdd(&g_cursor[d.z], 1);
        int p3 = atomicAdd(&g_cursor[d.w], 1);
        g_edata[p0] = make_int2(s.x | (t.x << 20), __float_as_int(nm.x));
        g_edata[p1] = make_int2(s.y | (t.y << 20), __float_as_int(nm.y));
        g_edata[p2] = make_int2(s.z | (t.z << 20), __float_as_int(nm.z));
        g_edata[p3] = make_int2(s.w | (t.w << 20), __float_as_int(nm.w));
    } else if (e0 < n_edges) {
        for (int e = e0; e < n_edges; ++e) {
            int d = __ldg(&dst[e]);
            int pos = atomicAdd(&g_cursor[d], 1);
            g_edata[pos] = make_int2(__ldg(&src[e]) | (__ldg(&etypes[e]) << 20),
                                     __float_as_int(__ldg(&norm[e])));
        }
    }
}

// ---------------------------------------------------------------------------
// Kernel 4: per-node aggregation, 8 lanes/node, uint4 gathers (R8 exact)
// ---------------------------------------------------------------------------
__device__ __forceinline__ void acc_msg(float4& a, float4& b, uint4 raw, float nm)
{
    float2 f0 = __half22float2(*reinterpret_cast<__half2*>(&raw.x));
    float2 f1 = __half22float2(*reinterpret_cast<__half2*>(&raw.y));
    float2 f2 = __half22float2(*reinterpret_cast<__half2*>(&raw.z));
    float2 f3 = __half22float2(*reinterpret_cast<__half2*>(&raw.w));
    a.x += f0.x * nm; a.y += f0.y * nm; a.z += f1.x * nm; a.w += f1.y * nm;
    b.x += f2.x * nm; b.y += f2.y * nm; b.z += f3.x * nm; b.w += f3.y * nm;
}

__global__ __launch_bounds__(256) void agg_kernel(
    float* __restrict__ out, int n_nodes)
{
    int gidx = blockIdx.x * 256 + threadIdx.x;
    int node = gidx >> 3;
    int lane = gidx & 7;
    if (node >= n_nodes) return;

    int start = __ldg(&g_offset[node]);
    int deg   = __ldg(&g_count[node]);

    float4 accA = *(float4*)&out[(size_t)node * OUT_FEAT + lane * 8];
    float4 accB = *(float4*)&out[(size_t)node * OUT_FEAT + lane * 8 + 4];

    int j = 0;
    for (; j + 4 <= deg; j += 4) {
        int2 e0 = __ldg(&g_edata[start + j + 0]);
        int2 e1 = __ldg(&g_edata[start + j + 1]);
        int2 e2 = __ldg(&g_edata[start + j + 2]);
        int2 e3 = __ldg(&g_edata[start + j + 3]);
        uint4 r0 = __ldg((const uint4*)(g_proj2 +
            ((size_t)(e0.x & 0xFFFFF) * P2_COLS + (e0.x >> 20) * OUT_FEAT + lane * 8)));
        uint4 r1 = __ldg((const uint4*)(g_proj2 +
            ((size_t)(e1.x & 0xFFFFF) * P2_COLS + (e1.x >> 20) * OUT_FEAT + lane * 8)));
        uint4 r2 = __ldg((const uint4*)(g_proj2 +
            ((size_t)(e2.x & 0xFFFFF) * P2_COLS + (e2.x >> 20) * OUT_FEAT + lane * 8)));
        uint4 r3 = __ldg((const uint4*)(g_proj2 +
            ((size_t)(e3.x & 0xFFFFF) * P2_COLS + (e3.x >> 20) * OUT_FEAT + lane * 8)));
        acc_msg(accA, accB, r0, __int_as_float(e0.y));
        acc_msg(accA, accB, r1, __int_as_float(e1.y));
        acc_msg(accA, accB, r2, __int_as_float(e2.y));
        acc_msg(accA, accB, r3, __int_as_float(e3.y));
    }
    for (; j < deg; ++j) {
        int2 ed = __ldg(&g_edata[start + j]);
        uint4 raw = __ldg((const uint4*)(g_proj2 +
            ((size_t)(ed.x & 0xFFFFF) * P2_COLS + (ed.x >> 20) * OUT_FEAT + lane * 8)));
        acc_msg(accA, accB, raw, __int_as_float(ed.y));
    }

    *(float4*)&out[(size_t)node * OUT_FEAT + lane * 8]     = accA;
    *(float4*)&out[(size_t)node * OUT_FEAT + lane * 8 + 4] = accB;
}

// ---------------------------------------------------------------------------
extern "C" void kernel_launch(void* const* d_in, const int* in_sizes, int n_in,
                              void* d_out, int out_size)
{
    const float* feat    = (const float*)d_in[0];
    const int*   src     = (const int*)d_in[1];
    const int*   dst     = (const int*)d_in[2];
    const int*   etypes  = (const int*)d_in[3];
    const float* norm    = (const float*)d_in[4];
    const float* weight  = (const float*)d_in[5];
    const float* w_comp  = (const float*)d_in[6];
    const float* h_bias  = (const float*)d_in[7];
    const float* loop_w  = (const float*)d_in[8];
    float*       out     = (float*)d_out;

    int n_nodes = in_sizes[0] / IN_FEAT;
    int n_edges = in_sizes[1];

    static bool attrSet = false;
    if (!attrSet) {
        cudaFuncSetAttribute(rgcn_mma_kernel,
                             cudaFuncAttributeMaxDynamicSharedMemorySize, SMEM_BYTES);
        attrSet = true;
    }

    // Phase 0: zero counters, combined weights
    zero_kernel<<<(n_nodes + 255) / 256, 256>>>(n_nodes);
    wcat_kernel<<<(IN_FEAT * WCAT_COLS + 255) / 256, 256>>>(weight, w_comp, loop_w);

    // Phase 1: HMMA GEMM with embedded dst-histogram
    rgcn_mma_kernel<<<(n_nodes + 127) / 128, 256, SMEM_BYTES>>>(
        feat, h_bias, dst, out, n_nodes, n_edges);

    // Phase 2: scan + scatter
    int nb = (n_nodes + SCAN_T - 1) / SCAN_T;
    scan_local_kernel<<<nb, SCAN_T>>>(n_nodes);
    scan_bsum_kernel<<<1, 128>>>(nb);
    scan_add_kernel<<<nb, SCAN_T>>>(n_nodes);
    int hthreads = (n_edges + 3) / 4;
    scatter_kernel<<<(hthreads + 255) / 256, 256>>>(src, dst, etypes, norm, n_edges);

    // Phase 3: atomic-free aggregation
    long long total_threads = (long long)n_nodes * 8;
    agg_kernel<<<(int)((total_threads + 255) / 256), 256>>>(out, n_nodes);
}